// round 1
// baseline (speedup 1.0000x reference)
#include <cuda_runtime.h>
#include <cstdint>

#define B_  64
#define C_  64
#define N_  1024
#define O_  128
#define K_  49
#define RT  16     // rows per CTA in knn kernel
#define TB  256    // threads per CTA in knn kernel
#define NCH 4      // node chunks in projection kernel
#define NPC (N_/NCH)

#define INF_F __int_as_float(0x7f800000)

// ---------------- scratch (device globals; no allocs allowed) ----------------
__device__ float g_Xt[B_*N_*C_];    // (b, n, c) node-major features
__device__ float g_Z [B_*N_*C_];    // (b, n, c) neighbor means
__device__ float g_part[B_*NCH*O_]; // partial relu-sums

// ---------------- f32x2 helpers (packed fp32 pair FMA, PTX-only) -------------
__device__ __forceinline__ unsigned long long pk2(float x) {
    unsigned long long r; unsigned u = __float_as_uint(x);
    asm("mov.b64 %0, {%1, %1};" : "=l"(r) : "r"(u));
    return r;
}
__device__ __forceinline__ unsigned long long fma2(unsigned long long a,
                                                   unsigned long long b,
                                                   unsigned long long c) {
    unsigned long long d;
    asm("fma.rn.f32x2 %0, %1, %2, %3;" : "=l"(d) : "l"(a), "l"(b), "l"(c));
    return d;
}
__device__ __forceinline__ float2 upk2(unsigned long long v) {
    unsigned lo, hi;
    asm("mov.b64 {%0, %1}, %2;" : "=r"(lo), "=r"(hi) : "l"(v));
    return make_float2(__uint_as_float(lo), __uint_as_float(hi));
}

// ---------------- kernel A: transpose X (b,c,n) -> Xt (b,n,c) ----------------
__global__ void k_transpose(const float* __restrict__ X) {
    __shared__ float tile[32][33];
    const int b  = blockIdx.z;
    const int nb = blockIdx.x * 32;
    const int cb = blockIdx.y * 32;
    const int tx = threadIdx.x, ty = threadIdx.y;
    const float* Xb = X + (size_t)b * C_ * N_;
    #pragma unroll
    for (int i = ty; i < 32; i += 8)
        tile[i][tx] = Xb[(cb + i) * N_ + nb + tx];
    __syncthreads();
    float* Xtb = g_Xt + (size_t)b * N_ * C_;
    #pragma unroll
    for (int i = ty; i < 32; i += 8)
        Xtb[(nb + i) * C_ + cb + tx] = tile[tx][i];
}

// ---------------- kernel B: fused distance + top-49 select + aggregate -------
struct SmemB {
    float    xiT[C_][RT];     // transposed query rows: [c][r]
    float    sqi[RT];
    float    d2[RT][N_];      // squared distances (clamped >= 0, diag = inf)
    int      sel[RT][64];     // selected neighbor indices (49 used)
    unsigned hist[256];
    unsigned wsum[8];
    unsigned maskLT[32];
    unsigned maskEQ[32];
    unsigned binfo[2];        // chosen bin, count strictly below bin
};

__device__ __forceinline__ unsigned rank_in_mask(const unsigned* mask, int j) {
    unsigned r = __popc(mask[j >> 5] & ((1u << (j & 31)) - 1u));
    const int w = j >> 5;
    for (int q = 0; q < w; q++) r += __popc(mask[q]);
    return r;
}

__global__ __launch_bounds__(TB) void k_knn(const float* __restrict__ X) {
    extern __shared__ char smem_raw[];
    SmemB& S = *reinterpret_cast<SmemB*>(smem_raw);

    const int b    = blockIdx.y;
    const int r0   = blockIdx.x * RT;
    const int tid  = threadIdx.x;
    const int lane = tid & 31;
    const int wid  = tid >> 5;

    const float* Xtb = g_Xt + (size_t)b * N_ * C_;

    // load 16 query rows, transposed into [c][r] (so 16 r-values are contiguous)
    for (int i = tid; i < RT * C_; i += TB) {
        int r = i >> 6, c = i & 63;
        S.xiT[c][r] = Xtb[(r0 + r) * C_ + c];
    }
    __syncthreads();
    if (tid < RT) {
        float s = 0.f;
        #pragma unroll
        for (int c = 0; c < C_; c++) { float v = S.xiT[c][tid]; s = fmaf(v, v, s); }
        S.sqi[tid] = s;
    }
    __syncthreads();

    float sqir[RT];
    #pragma unroll
    for (int r = 0; r < RT; r++) sqir[r] = S.sqi[r];

    // ---- distance phase: d2[r][j] = |xi_r|^2 + |x_j|^2 - 2 xi_r . x_j ----
    const float* Xb = X + (size_t)b * C_ * N_;
    #pragma unroll 1
    for (int jt = 0; jt < 2; jt++) {
        const int j0 = jt * 512 + tid;   // handles j0 and j0+256
        unsigned long long dp[2][8];
        #pragma unroll
        for (int u = 0; u < 2; u++)
            #pragma unroll
            for (int q = 0; q < 8; q++) dp[u][q] = 0ull;
        float sq0 = 0.f, sq1 = 0.f;
        #pragma unroll
        for (int c = 0; c < C_; c++) {
            const float x0 = Xb[c * N_ + j0];
            const float x1 = Xb[c * N_ + j0 + 256];
            const unsigned long long x0p = pk2(x0), x1p = pk2(x1);
            sq0 = fmaf(x0, x0, sq0);
            sq1 = fmaf(x1, x1, sq1);
            const ulonglong2* xr = reinterpret_cast<const ulonglong2*>(&S.xiT[c][0]);
            #pragma unroll
            for (int q = 0; q < 4; q++) {
                ulonglong2 a = xr[q];
                dp[0][2*q]   = fma2(a.x, x0p, dp[0][2*q]);
                dp[0][2*q+1] = fma2(a.y, x0p, dp[0][2*q+1]);
                dp[1][2*q]   = fma2(a.x, x1p, dp[1][2*q]);
                dp[1][2*q+1] = fma2(a.y, x1p, dp[1][2*q+1]);
            }
        }
        #pragma unroll
        for (int u = 0; u < 2; u++) {
            const int   j   = j0 + u * 256;
            const float sqj = u ? sq1 : sq0;
            #pragma unroll
            for (int p = 0; p < 8; p++) {
                float2 dd = upk2(dp[u][p]);
                float d0 = fmaxf(sqir[2*p]   + sqj - 2.f * dd.x, 0.f);
                float d1 = fmaxf(sqir[2*p+1] + sqj - 2.f * dd.y, 0.f);
                if (j == r0 + 2*p)     d0 = INF_F;
                if (j == r0 + 2*p + 1) d1 = INF_F;
                S.d2[2*p][j]   = d0;
                S.d2[2*p+1][j] = d1;
            }
        }
    }
    __syncthreads();

    // ---- selection phase: exact radix-select of 49 smallest per row ----
    #pragma unroll 1
    for (int r = 0; r < RT; r++) {
        unsigned want = K_, prefix = 0, below_total = 0;
        #pragma unroll
        for (int pass = 0; pass < 4; pass++) {
            const int shift = 24 - 8 * pass;
            S.hist[tid] = 0;
            __syncthreads();
            #pragma unroll
            for (int jt = 0; jt < 4; jt++) {
                const int j = jt * TB + tid;
                const unsigned key = __float_as_uint(S.d2[r][j]);
                const bool ok = (pass == 0) || ((key >> (shift + 8)) == prefix);
                if (ok) atomicAdd(&S.hist[(key >> shift) & 255u], 1u);
            }
            __syncthreads();
            const unsigned v = S.hist[tid];
            unsigned inc = v;
            #pragma unroll
            for (int off = 1; off < 32; off <<= 1) {
                unsigned n = __shfl_up_sync(0xffffffffu, inc, off);
                if (lane >= off) inc += n;
            }
            if (lane == 31) S.wsum[wid] = inc;
            __syncthreads();
            unsigned woff = 0;
            for (int w = 0; w < wid; w++) woff += S.wsum[w];
            const unsigned cum  = inc + woff;     // inclusive count over bins 0..tid
            const unsigned cume = cum - v;        // exclusive
            if (cum >= want && cume < want) { S.binfo[0] = (unsigned)tid; S.binfo[1] = cume; }
            __syncthreads();
            const unsigned bin = S.binfo[0], below = S.binfo[1];
            prefix       = (prefix << 8) | bin;
            want        -= below;
            below_total += below;
            __syncthreads();
        }
        const unsigned T    = prefix;   // exact key of 49th smallest
        const unsigned need = want;     // # of ties (== T) to keep, lowest index first

        if (tid < 32) { S.maskLT[tid] = 0; S.maskEQ[tid] = 0; }
        __syncthreads();
        #pragma unroll
        for (int jt = 0; jt < 4; jt++) {
            const int j = jt * TB + tid;
            const unsigned key = __float_as_uint(S.d2[r][j]);
            if (key < T)       atomicOr(&S.maskLT[j >> 5], 1u << (j & 31));
            else if (key == T) atomicOr(&S.maskEQ[j >> 5], 1u << (j & 31));
        }
        __syncthreads();
        #pragma unroll
        for (int jt = 0; jt < 4; jt++) {
            const int j = jt * TB + tid;
            const unsigned key = __float_as_uint(S.d2[r][j]);
            if (key < T) {
                const unsigned rk = rank_in_mask(S.maskLT, j);
                S.sel[r][rk] = j;
            } else if (key == T) {
                const unsigned rk = rank_in_mask(S.maskEQ, j);
                if (rk < need) S.sel[r][below_total + rk] = j;
            }
        }
        __syncthreads();
    }

    // ---- aggregation phase: z[r][c] = mean over 49 neighbors of Xt[j][c] ----
    const int c = tid & 63, g = tid >> 6;
    const float inv_k = 1.0f / (float)K_;
    #pragma unroll 1
    for (int r = g; r < RT; r += 4) {
        float acc = 0.f;
        #pragma unroll
        for (int k = 0; k < K_; k++) {
            const int j = S.sel[r][k];
            acc += Xtb[j * C_ + c];
        }
        g_Z[((size_t)b * N_ + r0 + r) * C_ + c] = acc * inv_k;
    }
}

// ---------------- kernel C: projection + ReLU + node-sum ----------------------
__global__ __launch_bounds__(O_) void k_proj(const float* __restrict__ W,
                                             const float* __restrict__ bias) {
    const int b  = blockIdx.y;
    const int ch = blockIdx.x;
    const int o  = threadIdx.x;

    float w[C_];
    #pragma unroll
    for (int c = 0; c < C_; c++) w[c] = W[o * C_ + c];
    const float bi = bias[o];

    __shared__ float4 s_z[8 * 16];   // 8 nodes x 64 floats
    const float4* Z4 =
        reinterpret_cast<const float4*>(g_Z + ((size_t)b * N_ + ch * NPC) * C_);

    float acc = 0.f;
    #pragma unroll 1
    for (int n0 = 0; n0 < NPC; n0 += 8) {
        s_z[o] = Z4[n0 * 16 + o];    // 128 float4 = 8 nodes
        __syncthreads();
        #pragma unroll
        for (int v = 0; v < 8; v++) {
            float d = 0.f;
            #pragma unroll
            for (int q = 0; q < 16; q++) {
                const float4 z = s_z[v * 16 + q];
                d = fmaf(w[4*q+0], z.x, d);
                d = fmaf(w[4*q+1], z.y, d);
                d = fmaf(w[4*q+2], z.z, d);
                d = fmaf(w[4*q+3], z.w, d);
            }
            acc += fmaxf(d + bi, 0.f);
        }
        __syncthreads();
    }
    g_part[((size_t)b * NCH + ch) * O_ + o] = acc;
}

// ---------------- kernel D: reduce chunks + BatchNorm affine ------------------
__global__ void k_final(const float* __restrict__ gamma,
                        const float* __restrict__ beta,
                        const float* __restrict__ rmean,
                        const float* __restrict__ rvar,
                        float* __restrict__ out) {
    const int i = blockIdx.x * 128 + threadIdx.x;  // 8192
    const int o = i & 127;
    const int b = i >> 7;
    float s = 0.f;
    #pragma unroll
    for (int ch = 0; ch < NCH; ch++) s += g_part[((size_t)b * NCH + ch) * O_ + o];
    const float m   = s * (1.0f / (float)N_);
    const float inv = rsqrtf(rvar[o] + 1e-5f);
    out[i] = gamma[o] * (m - rmean[o]) * inv + beta[o];
}

// ---------------- launch -----------------------------------------------------
extern "C" void kernel_launch(void* const* d_in, const int* in_sizes, int n_in,
                              void* d_out, int out_size) {
    (void)in_sizes; (void)n_in; (void)out_size;
    const float* X     = (const float*)d_in[0];
    const float* W     = (const float*)d_in[1];
    const float* bias  = (const float*)d_in[2];
    const float* gamma = (const float*)d_in[3];
    const float* beta  = (const float*)d_in[4];
    const float* rmean = (const float*)d_in[5];
    const float* rvar  = (const float*)d_in[6];
    float* out = (float*)d_out;

    dim3 gA(N_ / 32, C_ / 32, B_), bA(32, 8);
    k_transpose<<<gA, bA>>>(X);

    const int smemB = (int)sizeof(SmemB);
    cudaFuncSetAttribute(k_knn, cudaFuncAttributeMaxDynamicSharedMemorySize, smemB);
    k_knn<<<dim3(N_ / RT, B_), TB, smemB>>>(X);

    k_proj<<<dim3(NCH, B_), O_>>>(W, bias);
    k_final<<<B_ * O_ / 128, 128>>>(gamma, beta, rmean, rvar, out);
}

// round 2
// speedup vs baseline: 6.7578x; 6.7578x over previous
#include <cuda_runtime.h>
#include <cstdint>

#define B_  64
#define C_  64
#define N_  1024
#define O_  128
#define K_  49
#define RT  16     // rows per CTA in knn kernel (= warps per CTA)
#define TB  512    // threads per CTA in knn kernel
#define NCH 4      // node chunks in projection kernel
#define NPC (N_/NCH)

#define INF_F __int_as_float(0x7f800000)

// ---------------- scratch (device globals; no allocs allowed) ----------------
__device__ float g_Xt[B_*N_*C_];    // (b, n, c) node-major features
__device__ float g_Z [B_*N_*C_];    // (b, n, c) neighbor means
__device__ float g_part[B_*NCH*O_]; // partial relu-sums

// ---------------- f32x2 helpers (packed fp32 pair FMA, PTX-only) -------------
__device__ __forceinline__ unsigned long long pk2(float x) {
    unsigned long long r; unsigned u = __float_as_uint(x);
    asm("mov.b64 %0, {%1, %1};" : "=l"(r) : "r"(u));
    return r;
}
__device__ __forceinline__ unsigned long long fma2(unsigned long long a,
                                                   unsigned long long b,
                                                   unsigned long long c) {
    unsigned long long d;
    asm("fma.rn.f32x2 %0, %1, %2, %3;" : "=l"(d) : "l"(a), "l"(b), "l"(c));
    return d;
}
__device__ __forceinline__ float2 upk2(unsigned long long v) {
    unsigned lo, hi;
    asm("mov.b64 {%0, %1}, %2;" : "=r"(lo), "=r"(hi) : "l"(v));
    return make_float2(__uint_as_float(lo), __uint_as_float(hi));
}

// ---------------- kernel A: transpose X (b,c,n) -> Xt (b,n,c) ----------------
__global__ void k_transpose(const float* __restrict__ X) {
    __shared__ float tile[32][33];
    const int b  = blockIdx.z;
    const int nb = blockIdx.x * 32;
    const int cb = blockIdx.y * 32;
    const int tx = threadIdx.x, ty = threadIdx.y;
    const float* Xb = X + (size_t)b * C_ * N_;
    #pragma unroll
    for (int i = ty; i < 32; i += 8)
        tile[i][tx] = Xb[(cb + i) * N_ + nb + tx];
    __syncthreads();
    float* Xtb = g_Xt + (size_t)b * N_ * C_;
    #pragma unroll
    for (int i = ty; i < 32; i += 8)
        Xtb[(nb + i) * C_ + cb + tx] = tile[tx][i];
}

// ---------------- kernel B: fused distance + top-49 select + aggregate -------
struct SmemB {
    float xiT[C_][RT];     // transposed query rows: [c][r]
    float sqi[RT];
    float d2[RT][N_];      // squared distances (clamped >= 0, diag = inf)
    int   sel[RT][52];     // selected neighbor indices (49 used)
};

__global__ __launch_bounds__(TB) void k_knn(const float* __restrict__ X) {
    extern __shared__ char smem_raw[];
    SmemB& S = *reinterpret_cast<SmemB*>(smem_raw);

    const int b    = blockIdx.y;
    const int r0   = blockIdx.x * RT;
    const int tid  = threadIdx.x;
    const int lane = tid & 31;
    const int wid  = tid >> 5;        // 0..15

    const float* Xtb = g_Xt + (size_t)b * N_ * C_;

    // ---- load 16 query rows, transposed into [c][r] ----
    for (int i = tid; i < RT * C_; i += TB) {
        int r = i >> 6, c = i & 63;
        S.xiT[c][r] = Xtb[(r0 + r) * C_ + c];
    }
    __syncthreads();
    if (tid < RT) {
        float s = 0.f;
        #pragma unroll
        for (int c = 0; c < C_; c++) { float v = S.xiT[c][tid]; s = fmaf(v, v, s); }
        S.sqi[tid] = s;
    }
    __syncthreads();

    // ---- distance phase: d2[r][j] = |xi_r|^2 + |x_j|^2 - 2 xi_r . x_j ----
    // each thread handles j0 = tid and j1 = tid + 512, all 16 rows
    {
        const float* Xb = X + (size_t)b * C_ * N_;
        const int j0 = tid;
        unsigned long long dp[2][8];
        #pragma unroll
        for (int u = 0; u < 2; u++)
            #pragma unroll
            for (int q = 0; q < 8; q++) dp[u][q] = 0ull;
        float sq0 = 0.f, sq1 = 0.f;
        #pragma unroll
        for (int c = 0; c < C_; c++) {
            const float x0 = Xb[c * N_ + j0];
            const float x1 = Xb[c * N_ + j0 + 512];
            const unsigned long long x0p = pk2(x0), x1p = pk2(x1);
            sq0 = fmaf(x0, x0, sq0);
            sq1 = fmaf(x1, x1, sq1);
            const ulonglong2* xr = reinterpret_cast<const ulonglong2*>(&S.xiT[c][0]);
            #pragma unroll
            for (int q = 0; q < 4; q++) {
                ulonglong2 a = xr[q];
                dp[0][2*q]   = fma2(a.x, x0p, dp[0][2*q]);
                dp[0][2*q+1] = fma2(a.y, x0p, dp[0][2*q+1]);
                dp[1][2*q]   = fma2(a.x, x1p, dp[1][2*q]);
                dp[1][2*q+1] = fma2(a.y, x1p, dp[1][2*q+1]);
            }
        }
        #pragma unroll
        for (int u = 0; u < 2; u++) {
            const int   j   = j0 + u * 512;
            const float sqj = u ? sq1 : sq0;
            #pragma unroll
            for (int p = 0; p < 8; p++) {
                float2 dd = upk2(dp[u][p]);
                float d0 = fmaxf(S.sqi[2*p]   + sqj - 2.f * dd.x, 0.f);
                float d1 = fmaxf(S.sqi[2*p+1] + sqj - 2.f * dd.y, 0.f);
                if (j == r0 + 2*p)     d0 = INF_F;
                if (j == r0 + 2*p + 1) d1 = INF_F;
                S.d2[2*p][j]   = d0;
                S.d2[2*p+1][j] = d1;
            }
        }
    }
    __syncthreads();

    // ---- selection phase: one warp per row, exact top-49 by binary search ----
    {
        const int r = wid;
        // lane holds keys for j = lane + 32*m  (monotone in (m, lane) -> j order)
        unsigned key[32];
        #pragma unroll
        for (int m = 0; m < 32; m++)
            key[m] = __float_as_uint(S.d2[r][lane + 32 * m]);

        // T = largest x with count(keys < x) < K  == exact 49th-smallest key
        unsigned T = 0;
        #pragma unroll 1
        for (int bit = 31; bit >= 0; bit--) {
            const unsigned cand = T | (1u << bit);
            unsigned c = 0;
            #pragma unroll
            for (int m = 0; m < 32; m++) c += (key[m] - cand) >> 31;  // key < cand
            c += __shfl_xor_sync(0xffffffffu, c, 16);
            c += __shfl_xor_sync(0xffffffffu, c, 8);
            c += __shfl_xor_sync(0xffffffffu, c, 4);
            c += __shfl_xor_sync(0xffffffffu, c, 2);
            c += __shfl_xor_sync(0xffffffffu, c, 1);
            if (c < K_) T = cand;
        }
        // below = count(keys < T)
        unsigned below = 0;
        #pragma unroll
        for (int m = 0; m < 32; m++) below += (key[m] - T) >> 31;
        below += __shfl_xor_sync(0xffffffffu, below, 16);
        below += __shfl_xor_sync(0xffffffffu, below, 8);
        below += __shfl_xor_sync(0xffffffffu, below, 4);
        below += __shfl_xor_sync(0xffffffffu, below, 2);
        below += __shfl_xor_sync(0xffffffffu, below, 1);
        const unsigned need = K_ - below;   // ties == T to keep, lowest j first

        int* sel = S.sel[r];
        const unsigned lanemask = (lane == 0) ? 0u : (0xffffffffu >> (32 - lane));
        unsigned base = 0, tie_taken = 0;
        #pragma unroll
        for (int m = 0; m < 32; m++) {
            const unsigned k  = key[m];
            const bool lt = (k < T), eq = (k == T);
            const unsigned mlt = __ballot_sync(0xffffffffu, lt);
            const unsigned meq = __ballot_sync(0xffffffffu, eq);
            if (lt) sel[base + __popc(mlt & lanemask)] = lane + 32 * m;
            if (eq) {
                const unsigned rk = tie_taken + __popc(meq & lanemask);
                if (rk < need) sel[below + rk] = lane + 32 * m;
            }
            base      += __popc(mlt);
            tie_taken += __popc(meq);
        }
    }
    __syncthreads();

    // ---- aggregation phase: z[r][c] = mean over 49 neighbors of Xt[j][c] ----
    {
        const int c = tid & 63, g = tid >> 6;   // 8 groups of 64 threads
        const float inv_k = 1.0f / (float)K_;
        #pragma unroll 1
        for (int r = g; r < RT; r += 8) {
            float acc = 0.f;
            #pragma unroll
            for (int k = 0; k < K_; k++) {
                const int j = S.sel[r][k];
                acc += Xtb[j * C_ + c];
            }
            g_Z[((size_t)b * N_ + r0 + r) * C_ + c] = acc * inv_k;
        }
    }
}

// ---------------- kernel C: projection + ReLU + node-sum ----------------------
__global__ __launch_bounds__(O_) void k_proj(const float* __restrict__ W,
                                             const float* __restrict__ bias) {
    const int b  = blockIdx.y;
    const int ch = blockIdx.x;
    const int o  = threadIdx.x;

    float w[C_];
    #pragma unroll
    for (int c = 0; c < C_; c++) w[c] = W[o * C_ + c];
    const float bi = bias[o];

    __shared__ float4 s_z[8 * 16];   // 8 nodes x 64 floats
    const float4* Z4 =
        reinterpret_cast<const float4*>(g_Z + ((size_t)b * N_ + ch * NPC) * C_);

    float acc = 0.f;
    #pragma unroll 1
    for (int n0 = 0; n0 < NPC; n0 += 8) {
        s_z[o] = Z4[n0 * 16 + o];    // 128 float4 = 8 nodes
        __syncthreads();
        #pragma unroll
        for (int v = 0; v < 8; v++) {
            float d = 0.f;
            #pragma unroll
            for (int q = 0; q < 16; q++) {
                const float4 z = s_z[v * 16 + q];
                d = fmaf(w[4*q+0], z.x, d);
                d = fmaf(w[4*q+1], z.y, d);
                d = fmaf(w[4*q+2], z.z, d);
                d = fmaf(w[4*q+3], z.w, d);
            }
            acc += fmaxf(d + bi, 0.f);
        }
        __syncthreads();
    }
    g_part[((size_t)b * NCH + ch) * O_ + o] = acc;
}

// ---------------- kernel D: reduce chunks + BatchNorm affine ------------------
__global__ void k_final(const float* __restrict__ gamma,
                        const float* __restrict__ beta,
                        const float* __restrict__ rmean,
                        const float* __restrict__ rvar,
                        float* __restrict__ out) {
    const int i = blockIdx.x * 128 + threadIdx.x;  // 8192
    const int o = i & 127;
    const int b = i >> 7;
    float s = 0.f;
    #pragma unroll
    for (int ch = 0; ch < NCH; ch++) s += g_part[((size_t)b * NCH + ch) * O_ + o];
    const float m   = s * (1.0f / (float)N_);
    const float inv = rsqrtf(rvar[o] + 1e-5f);
    out[i] = gamma[o] * (m - rmean[o]) * inv + beta[o];
}

// ---------------- launch -----------------------------------------------------
extern "C" void kernel_launch(void* const* d_in, const int* in_sizes, int n_in,
                              void* d_out, int out_size) {
    (void)in_sizes; (void)n_in; (void)out_size;
    const float* X     = (const float*)d_in[0];
    const float* W     = (const float*)d_in[1];
    const float* bias  = (const float*)d_in[2];
    const float* gamma = (const float*)d_in[3];
    const float* beta  = (const float*)d_in[4];
    const float* rmean = (const float*)d_in[5];
    const float* rvar  = (const float*)d_in[6];
    float* out = (float*)d_out;

    dim3 gA(N_ / 32, C_ / 32, B_), bA(32, 8);
    k_transpose<<<gA, bA>>>(X);

    const int smemB = (int)sizeof(SmemB);
    cudaFuncSetAttribute(k_knn, cudaFuncAttributeMaxDynamicSharedMemorySize, smemB);
    k_knn<<<dim3(N_ / RT, B_), TB, smemB>>>(X);

    k_proj<<<dim3(NCH, B_), O_>>>(W, bias);
    k_final<<<B_ * O_ / 128, 128>>>(gamma, beta, rmean, rvar, out);
}

// round 3
// speedup vs baseline: 6.7649x; 1.0010x over previous
#include <cuda_runtime.h>
#include <cstdint>

#define B_  64
#define C_  64
#define N_  1024
#define O_  128
#define K_  49
#define RT  16     // rows per CTA in knn kernel (= warps per CTA)
#define TB  512    // threads per CTA in knn kernel
#define NCH 4      // node chunks in projection kernel
#define NPC (N_/NCH)

#define INF_F __int_as_float(0x7f800000)

// ---------------- scratch (device globals; no allocs allowed) ----------------
__device__ float g_Xt[B_*N_*C_];    // (b, n, c) node-major features
__device__ float g_Z [B_*N_*C_];    // (b, n, c) neighbor means
__device__ float g_part[B_*NCH*O_]; // partial relu-sums

// ---------------- f32x2 helpers (packed fp32 pair FMA, PTX-only) -------------
__device__ __forceinline__ unsigned long long pk2(float x) {
    unsigned long long r; unsigned u = __float_as_uint(x);
    asm("mov.b64 %0, {%1, %1};" : "=l"(r) : "r"(u));
    return r;
}
__device__ __forceinline__ unsigned long long fma2(unsigned long long a,
                                                   unsigned long long b,
                                                   unsigned long long c) {
    unsigned long long d;
    asm("fma.rn.f32x2 %0, %1, %2, %3;" : "=l"(d) : "l"(a), "l"(b), "l"(c));
    return d;
}
__device__ __forceinline__ float2 upk2(unsigned long long v) {
    unsigned lo, hi;
    asm("mov.b64 {%0, %1}, %2;" : "=r"(lo), "=r"(hi) : "l"(v));
    return make_float2(__uint_as_float(lo), __uint_as_float(hi));
}

// ---------------- kernel A: transpose X (b,c,n) -> Xt (b,n,c) ----------------
__global__ void k_transpose(const float* __restrict__ X) {
    __shared__ float tile[32][33];
    const int b  = blockIdx.z;
    const int nb = blockIdx.x * 32;
    const int cb = blockIdx.y * 32;
    const int tx = threadIdx.x, ty = threadIdx.y;
    const float* Xb = X + (size_t)b * C_ * N_;
    #pragma unroll
    for (int i = ty; i < 32; i += 8)
        tile[i][tx] = Xb[(cb + i) * N_ + nb + tx];
    __syncthreads();
    float* Xtb = g_Xt + (size_t)b * N_ * C_;
    #pragma unroll
    for (int i = ty; i < 32; i += 8)
        Xtb[(nb + i) * C_ + cb + tx] = tile[tx][i];
}

// ---------------- kernel B: fused distance + top-49 select + aggregate -------
struct SmemB {
    float xiT[C_][RT];     // transposed query rows: [c][r]
    float sqi[RT];
    float d2[RT][N_];      // squared distances (clamped >= 0, diag = inf)
    int   sel[RT][52];     // selected neighbor indices (49 used)
};

__global__ __launch_bounds__(TB) void k_knn(const float* __restrict__ X) {
    extern __shared__ char smem_raw[];
    SmemB& S = *reinterpret_cast<SmemB*>(smem_raw);

    const int b    = blockIdx.y;
    const int r0   = blockIdx.x * RT;
    const int tid  = threadIdx.x;
    const int lane = tid & 31;
    const int wid  = tid >> 5;        // 0..15

    const float* Xtb = g_Xt + (size_t)b * N_ * C_;

    // ---- load 16 query rows, transposed into [c][r] ----
    for (int i = tid; i < RT * C_; i += TB) {
        int r = i >> 6, c = i & 63;
        S.xiT[c][r] = Xtb[(r0 + r) * C_ + c];
    }
    __syncthreads();
    if (tid < RT) {
        float s = 0.f;
        #pragma unroll
        for (int c = 0; c < C_; c++) { float v = S.xiT[c][tid]; s = fmaf(v, v, s); }
        S.sqi[tid] = s;
    }
    __syncthreads();

    // ---- distance phase: d2[r][j] = |xi_r|^2 + |x_j|^2 - 2 xi_r . x_j ----
    // each thread handles j0 = tid and j1 = tid + 512, all 16 rows
    {
        const float* Xb = X + (size_t)b * C_ * N_;
        const int j0 = tid;
        unsigned long long dp[2][8];
        #pragma unroll
        for (int u = 0; u < 2; u++)
            #pragma unroll
            for (int q = 0; q < 8; q++) dp[u][q] = 0ull;
        float sq0 = 0.f, sq1 = 0.f;
        #pragma unroll
        for (int c = 0; c < C_; c++) {
            const float x0 = Xb[c * N_ + j0];
            const float x1 = Xb[c * N_ + j0 + 512];
            const unsigned long long x0p = pk2(x0), x1p = pk2(x1);
            sq0 = fmaf(x0, x0, sq0);
            sq1 = fmaf(x1, x1, sq1);
            const ulonglong2* xr = reinterpret_cast<const ulonglong2*>(&S.xiT[c][0]);
            #pragma unroll
            for (int q = 0; q < 4; q++) {
                ulonglong2 a = xr[q];
                dp[0][2*q]   = fma2(a.x, x0p, dp[0][2*q]);
                dp[0][2*q+1] = fma2(a.y, x0p, dp[0][2*q+1]);
                dp[1][2*q]   = fma2(a.x, x1p, dp[1][2*q]);
                dp[1][2*q+1] = fma2(a.y, x1p, dp[1][2*q+1]);
            }
        }
        #pragma unroll
        for (int u = 0; u < 2; u++) {
            const int   j   = j0 + u * 512;
            const float sqj = u ? sq1 : sq0;
            #pragma unroll
            for (int p = 0; p < 8; p++) {
                float2 dd = upk2(dp[u][p]);
                float d0 = fmaxf(S.sqi[2*p]   + sqj - 2.f * dd.x, 0.f);
                float d1 = fmaxf(S.sqi[2*p+1] + sqj - 2.f * dd.y, 0.f);
                if (j == r0 + 2*p)     d0 = INF_F;
                if (j == r0 + 2*p + 1) d1 = INF_F;
                S.d2[2*p][j]   = d0;
                S.d2[2*p+1][j] = d1;
            }
        }
    }
    __syncthreads();

    // ---- selection phase: one warp per row, exact top-49 by binary search ----
    {
        const int r = wid;
        // lane holds keys for j = lane + 32*m  (monotone in (m, lane) -> j order)
        unsigned key[32];
        #pragma unroll
        for (int m = 0; m < 32; m++)
            key[m] = __float_as_uint(S.d2[r][lane + 32 * m]);

        // T = largest x with count(keys < x) < K  == exact 49th-smallest key
        unsigned T = 0;
        #pragma unroll 1
        for (int bit = 31; bit >= 0; bit--) {
            const unsigned cand = T | (1u << bit);
            unsigned c = 0;
            #pragma unroll
            for (int m = 0; m < 32; m++) c += (key[m] - cand) >> 31;  // key < cand
            c += __shfl_xor_sync(0xffffffffu, c, 16);
            c += __shfl_xor_sync(0xffffffffu, c, 8);
            c += __shfl_xor_sync(0xffffffffu, c, 4);
            c += __shfl_xor_sync(0xffffffffu, c, 2);
            c += __shfl_xor_sync(0xffffffffu, c, 1);
            if (c < K_) T = cand;
        }
        // below = count(keys < T)
        unsigned below = 0;
        #pragma unroll
        for (int m = 0; m < 32; m++) below += (key[m] - T) >> 31;
        below += __shfl_xor_sync(0xffffffffu, below, 16);
        below += __shfl_xor_sync(0xffffffffu, below, 8);
        below += __shfl_xor_sync(0xffffffffu, below, 4);
        below += __shfl_xor_sync(0xffffffffu, below, 2);
        below += __shfl_xor_sync(0xffffffffu, below, 1);
        const unsigned need = K_ - below;   // ties == T to keep, lowest j first

        int* sel = S.sel[r];
        const unsigned lanemask = (lane == 0) ? 0u : (0xffffffffu >> (32 - lane));
        unsigned base = 0, tie_taken = 0;
        #pragma unroll
        for (int m = 0; m < 32; m++) {
            const unsigned k  = key[m];
            const bool lt = (k < T), eq = (k == T);
            const unsigned mlt = __ballot_sync(0xffffffffu, lt);
            const unsigned meq = __ballot_sync(0xffffffffu, eq);
            if (lt) sel[base + __popc(mlt & lanemask)] = lane + 32 * m;
            if (eq) {
                const unsigned rk = tie_taken + __popc(meq & lanemask);
                if (rk < need) sel[below + rk] = lane + 32 * m;
            }
            base      += __popc(mlt);
            tie_taken += __popc(meq);
        }
    }
    __syncthreads();

    // ---- aggregation phase: z[r][c] = mean over 49 neighbors of Xt[j][c] ----
    {
        const int c = tid & 63, g = tid >> 6;   // 8 groups of 64 threads
        const float inv_k = 1.0f / (float)K_;
        #pragma unroll 1
        for (int r = g; r < RT; r += 8) {
            float acc = 0.f;
            #pragma unroll
            for (int k = 0; k < K_; k++) {
                const int j = S.sel[r][k];
                acc += Xtb[j * C_ + c];
            }
            g_Z[((size_t)b * N_ + r0 + r) * C_ + c] = acc * inv_k;
        }
    }
}

// ---------------- kernel C: projection + ReLU + node-sum ----------------------
__global__ __launch_bounds__(O_) void k_proj(const float* __restrict__ W,
                                             const float* __restrict__ bias) {
    const int b  = blockIdx.y;
    const int ch = blockIdx.x;
    const int o  = threadIdx.x;

    float w[C_];
    #pragma unroll
    for (int c = 0; c < C_; c++) w[c] = W[o * C_ + c];
    const float bi = bias[o];

    __shared__ float4 s_z[8 * 16];   // 8 nodes x 64 floats
    const float4* Z4 =
        reinterpret_cast<const float4*>(g_Z + ((size_t)b * N_ + ch * NPC) * C_);

    float acc = 0.f;
    #pragma unroll 1
    for (int n0 = 0; n0 < NPC; n0 += 8) {
        s_z[o] = Z4[n0 * 16 + o];    // 128 float4 = 8 nodes
        __syncthreads();
        #pragma unroll
        for (int v = 0; v < 8; v++) {
            float d = 0.f;
            #pragma unroll
            for (int q = 0; q < 16; q++) {
                const float4 z = s_z[v * 16 + q];
                d = fmaf(w[4*q+0], z.x, d);
                d = fmaf(w[4*q+1], z.y, d);
                d = fmaf(w[4*q+2], z.z, d);
                d = fmaf(w[4*q+3], z.w, d);
            }
            acc += fmaxf(d + bi, 0.f);
        }
        __syncthreads();
    }
    g_part[((size_t)b * NCH + ch) * O_ + o] = acc;
}

// ---------------- kernel D: reduce chunks + BatchNorm affine ------------------
__global__ void k_final(const float* __restrict__ gamma,
                        const float* __restrict__ beta,
                        const float* __restrict__ rmean,
                        const float* __restrict__ rvar,
                        float* __restrict__ out) {
    const int i = blockIdx.x * 128 + threadIdx.x;  // 8192
    const int o = i & 127;
    const int b = i >> 7;
    float s = 0.f;
    #pragma unroll
    for (int ch = 0; ch < NCH; ch++) s += g_part[((size_t)b * NCH + ch) * O_ + o];
    const float m   = s * (1.0f / (float)N_);
    const float inv = rsqrtf(rvar[o] + 1e-5f);
    out[i] = gamma[o] * (m - rmean[o]) * inv + beta[o];
}

// ---------------- launch -----------------------------------------------------
extern "C" void kernel_launch(void* const* d_in, const int* in_sizes, int n_in,
                              void* d_out, int out_size) {
    (void)in_sizes; (void)n_in; (void)out_size;
    const float* X     = (const float*)d_in[0];
    const float* W     = (const float*)d_in[1];
    const float* bias  = (const float*)d_in[2];
    const float* gamma = (const float*)d_in[3];
    const float* beta  = (const float*)d_in[4];
    const float* rmean = (const float*)d_in[5];
    const float* rvar  = (const float*)d_in[6];
    float* out = (float*)d_out;

    dim3 gA(N_ / 32, C_ / 32, B_), bA(32, 8);
    k_transpose<<<gA, bA>>>(X);

    const int smemB = (int)sizeof(SmemB);
    cudaFuncSetAttribute(k_knn, cudaFuncAttributeMaxDynamicSharedMemorySize, smemB);
    k_knn<<<dim3(N_ / RT, B_), TB, smemB>>>(X);

    k_proj<<<dim3(NCH, B_), O_>>>(W, bias);
    k_final<<<B_ * O_ / 128, 128>>>(gamma, beta, rmean, rvar, out);
}